// round 1
// baseline (speedup 1.0000x reference)
#include <cuda_runtime.h>
#include <math.h>

// Problem constants
#define BB 4
#define NN 1024
#define DM 1024
#define NH 16
#define DK 64

// Scratch (allocation-free rule: __device__ globals)
__device__ float g_q[BB * NN * DM];
__device__ float g_k[BB * NN * DM];
__device__ float g_v[BB * NN * DM];
__device__ float g_ctx[BB * NN * DM];

// ---------------------------------------------------------------------------
// GEMM: C[M,1024] = (A[M,1024] @ W[1024,1024] + bias) * scale
// Block tile 128x64, BK=32, 256 threads, per-thread 8x4 micro-tile.
// ---------------------------------------------------------------------------
__global__ __launch_bounds__(256) void gemm_kernel(
    const float* __restrict__ A, const float* __restrict__ W,
    const float* __restrict__ bias, float* __restrict__ C, float scale)
{
    const int K = 1024, NC = 1024;
    __shared__ float As[128 * 36];   // pad 36 (16B-aligned rows)
    __shared__ float Bs[32 * 68];    // pad 68 (16B-aligned rows)

    const int tid = threadIdx.x;
    const int tx = tid & 15;         // 0..15 -> n
    const int ty = tid >> 4;         // 0..15 -> m
    const int m0 = blockIdx.y << 7;  // 128-row tiles
    const int n0 = blockIdx.x << 6;  // 64-col tiles

    float acc[8][4];
    #pragma unroll
    for (int i = 0; i < 8; i++)
        #pragma unroll
        for (int j = 0; j < 4; j++) acc[i][j] = 0.0f;

    for (int k0 = 0; k0 < K; k0 += 32) {
        // Load A tile 128x32 (1024 float4, 4 per thread)
        #pragma unroll
        for (int t = 0; t < 4; t++) {
            int idx = tid + (t << 8);
            int r = idx >> 3;
            int c = (idx & 7) << 2;
            float4 v = *(const float4*)(A + (size_t)(m0 + r) * K + k0 + c);
            *(float4*)&As[r * 36 + c] = v;
        }
        // Load W tile 32x64 (512 float4, 2 per thread)
        #pragma unroll
        for (int t = 0; t < 2; t++) {
            int idx = tid + (t << 8);
            int r = idx >> 4;
            int c = (idx & 15) << 2;
            *(float4*)&Bs[r * 68 + c] =
                *(const float4*)(W + (size_t)(k0 + r) * NC + n0 + c);
        }
        __syncthreads();

        #pragma unroll
        for (int kk = 0; kk < 32; kk++) {
            float a[8];
            #pragma unroll
            for (int i = 0; i < 8; i++) a[i] = As[(ty * 8 + i) * 36 + kk];
            float4 bv = *(float4*)&Bs[kk * 68 + (tx << 2)];
            float b[4] = {bv.x, bv.y, bv.z, bv.w};
            #pragma unroll
            for (int i = 0; i < 8; i++)
                #pragma unroll
                for (int j = 0; j < 4; j++)
                    acc[i][j] = fmaf(a[i], b[j], acc[i][j]);
        }
        __syncthreads();
    }

    float4 bb = *(const float4*)(bias + n0 + (tx << 2));
    #pragma unroll
    for (int i = 0; i < 8; i++) {
        int row = m0 + ty * 8 + i;
        float4 o;
        o.x = (acc[i][0] + bb.x) * scale;
        o.y = (acc[i][1] + bb.y) * scale;
        o.z = (acc[i][2] + bb.z) * scale;
        o.w = (acc[i][3] + bb.w) * scale;
        *(float4*)(C + (size_t)row * NC + n0 + (tx << 2)) = o;
    }
}

// ---------------------------------------------------------------------------
// Attention: per (b,h, 64-query tile), flash-style online softmax over 16
// key tiles of 64. Q pre-scaled by 1/8. ctx -> g_ctx in [b,n,h*64+d] layout.
// 256 threads: 16x16, each owns a 4x4 micro-tile of the 64x64 S / acc tiles.
// ---------------------------------------------------------------------------
#define QS_STRIDE 68
#define KS_STRIDE 65
#define VS_STRIDE 68
#define PS_STRIDE 68
#define ATTN_SMEM ((64 * (QS_STRIDE + KS_STRIDE + VS_STRIDE + PS_STRIDE)) * 4)

__global__ __launch_bounds__(256) void attn_kernel(const float* __restrict__ bias)
{
    extern __shared__ float sh[];
    float* Qs = sh;                      // 64 x 68
    float* Ks = Qs + 64 * QS_STRIDE;     // 64 x 65
    float* Vs = Ks + 64 * KS_STRIDE;     // 64 x 68
    float* Ps = Vs + 64 * VS_STRIDE;     // 64 x 68

    const int qt = blockIdx.x;   // query tile 0..15
    const int h  = blockIdx.y;   // head
    const int b  = blockIdx.z;   // batch
    const int tid = threadIdx.x;
    const int tx = tid & 15;
    const int ty = tid >> 4;

    const float* Qg = g_q + ((size_t)(b * NN + qt * 64)) * DM + h * DK;
    // Load Q tile 64x64 (1024 float4, 4 per thread)
    #pragma unroll
    for (int t = 0; t < 4; t++) {
        int idx = tid + (t << 8);
        int r = idx >> 4;
        int c = (idx & 15) << 2;
        *(float4*)&Qs[r * QS_STRIDE + c] = *(const float4*)(Qg + (size_t)r * DM + c);
    }

    float m_r[4], l_r[4], acc[4][4];
    #pragma unroll
    for (int i = 0; i < 4; i++) {
        m_r[i] = -1e30f;
        l_r[i] = 0.0f;
        #pragma unroll
        for (int j = 0; j < 4; j++) acc[i][j] = 0.0f;
    }

    const float* biasg = bias + (((size_t)(b * NH + h)) * NN + qt * 64) * NN;

    for (int kt = 0; kt < 16; kt++) {
        __syncthreads();  // previous iteration's PV done before overwrite
        const float* Kg = g_k + ((size_t)(b * NN + kt * 64)) * DM + h * DK;
        const float* Vg = g_v + ((size_t)(b * NN + kt * 64)) * DM + h * DK;
        #pragma unroll
        for (int t = 0; t < 4; t++) {
            int idx = tid + (t << 8);
            int r = idx >> 4;
            int c = (idx & 15) << 2;
            float4 kv = *(const float4*)(Kg + (size_t)r * DM + c);
            Ks[r * KS_STRIDE + c + 0] = kv.x;
            Ks[r * KS_STRIDE + c + 1] = kv.y;
            Ks[r * KS_STRIDE + c + 2] = kv.z;
            Ks[r * KS_STRIDE + c + 3] = kv.w;
            *(float4*)&Vs[r * VS_STRIDE + c] = *(const float4*)(Vg + (size_t)r * DM + c);
        }
        __syncthreads();

        // S = Q @ K^T (64x64, inner d=64)
        float s[4][4];
        #pragma unroll
        for (int i = 0; i < 4; i++)
            #pragma unroll
            for (int j = 0; j < 4; j++) s[i][j] = 0.0f;

        #pragma unroll
        for (int d = 0; d < 64; d++) {
            float a[4], kk[4];
            #pragma unroll
            for (int i = 0; i < 4; i++) a[i] = Qs[(ty * 4 + i) * QS_STRIDE + d];
            #pragma unroll
            for (int j = 0; j < 4; j++) kk[j] = Ks[(tx * 4 + j) * KS_STRIDE + d];
            #pragma unroll
            for (int i = 0; i < 4; i++)
                #pragma unroll
                for (int j = 0; j < 4; j++)
                    s[i][j] = fmaf(a[i], kk[j], s[i][j]);
        }

        // + bias, then online softmax update per row
        #pragma unroll
        for (int i = 0; i < 4; i++) {
            float4 bb = *(const float4*)(biasg + (size_t)(ty * 4 + i) * NN + kt * 64 + (tx << 2));
            s[i][0] += bb.x; s[i][1] += bb.y; s[i][2] += bb.z; s[i][3] += bb.w;

            float tmax = fmaxf(fmaxf(s[i][0], s[i][1]), fmaxf(s[i][2], s[i][3]));
            #pragma unroll
            for (int o = 8; o >= 1; o >>= 1)
                tmax = fmaxf(tmax, __shfl_xor_sync(0xffffffffu, tmax, o));

            float mnew = fmaxf(m_r[i], tmax);
            float sc = __expf(m_r[i] - mnew);
            float rs = 0.0f;
            #pragma unroll
            for (int j = 0; j < 4; j++) {
                s[i][j] = __expf(s[i][j] - mnew);
                rs += s[i][j];
            }
            #pragma unroll
            for (int o = 8; o >= 1; o >>= 1)
                rs += __shfl_xor_sync(0xffffffffu, rs, o);

            l_r[i] = l_r[i] * sc + rs;
            m_r[i] = mnew;
            #pragma unroll
            for (int j = 0; j < 4; j++) acc[i][j] *= sc;

            *(float4*)&Ps[(ty * 4 + i) * PS_STRIDE + (tx << 2)] =
                make_float4(s[i][0], s[i][1], s[i][2], s[i][3]);
        }
        __syncthreads();

        // acc += P @ V (64x64, inner k=64)
        #pragma unroll
        for (int k = 0; k < 64; k++) {
            float p[4];
            #pragma unroll
            for (int i = 0; i < 4; i++) p[i] = Ps[(ty * 4 + i) * PS_STRIDE + k];
            float4 vv = *(float4*)&Vs[k * VS_STRIDE + (tx << 2)];
            float v4[4] = {vv.x, vv.y, vv.z, vv.w};
            #pragma unroll
            for (int i = 0; i < 4; i++)
                #pragma unroll
                for (int j = 0; j < 4; j++)
                    acc[i][j] = fmaf(p[i], v4[j], acc[i][j]);
        }
    }

    float* Og = g_ctx + ((size_t)(b * NN + qt * 64)) * DM + h * DK;
    #pragma unroll
    for (int i = 0; i < 4; i++) {
        float inv = 1.0f / l_r[i];
        float4 o = make_float4(acc[i][0] * inv, acc[i][1] * inv,
                               acc[i][2] * inv, acc[i][3] * inv);
        *(float4*)(Og + (size_t)(ty * 4 + i) * DM + (tx << 2)) = o;
    }
}

// ---------------------------------------------------------------------------
// Launch
// ---------------------------------------------------------------------------
extern "C" void kernel_launch(void* const* d_in, const int* in_sizes, int n_in,
                              void* d_out, int out_size)
{
    const float* queries   = (const float*)d_in[0];
    const float* keys      = (const float*)d_in[1];
    const float* values    = (const float*)d_in[2];
    const float* attn_bias = (const float*)d_in[3];
    const float* Wq = (const float*)d_in[4];
    const float* bq = (const float*)d_in[5];
    const float* Wk = (const float*)d_in[6];
    const float* bk = (const float*)d_in[7];
    const float* Wv = (const float*)d_in[8];
    const float* bv = (const float*)d_in[9];
    const float* Wo = (const float*)d_in[10];
    const float* bo = (const float*)d_in[11];
    float* out = (float*)d_out;

    float *q, *k, *v, *ctx;
    cudaGetSymbolAddress((void**)&q,   g_q);
    cudaGetSymbolAddress((void**)&k,   g_k);
    cudaGetSymbolAddress((void**)&v,   g_v);
    cudaGetSymbolAddress((void**)&ctx, g_ctx);

    cudaFuncSetAttribute(attn_kernel,
                         cudaFuncAttributeMaxDynamicSharedMemorySize, ATTN_SMEM);

    dim3 gemm_grid(1024 / 64, (BB * NN) / 128);  // (16, 32)
    gemm_kernel<<<gemm_grid, 256>>>(queries, Wq, bq, q, 0.125f);  // D_KEY^-0.5
    gemm_kernel<<<gemm_grid, 256>>>(keys,    Wk, bk, k, 1.0f);
    gemm_kernel<<<gemm_grid, 256>>>(values,  Wv, bv, v, 1.0f);

    attn_kernel<<<dim3(16, 16, 4), 256, ATTN_SMEM>>>(attn_bias);

    gemm_kernel<<<gemm_grid, 256>>>(ctx, Wo, bo, out, 1.0f);
}

// round 3
// speedup vs baseline: 1.6216x; 1.6216x over previous
#include <cuda_runtime.h>
#include <cuda_bf16.h>
#include <math.h>
#include <stdint.h>

// Problem constants
#define BB 4
#define NN 1024
#define DM 1024
#define NH 16
#define DK 64

// ---------------------------------------------------------------------------
// Scratch (__device__ globals; allocation-free rule)
// ---------------------------------------------------------------------------
__device__ float g_q[BB * NN * DM];
__device__ float g_k[BB * NN * DM];
__device__ float g_v[BB * NN * DM];
__device__ float g_ctx[BB * NN * DM];

#define ACT_ELEMS (4096 * 1024)
#define W_ELEMS   (1024 * 1024)
__device__ __align__(16) __nv_bfloat16 g_ah[3ull * ACT_ELEMS];
__device__ __align__(16) __nv_bfloat16 g_al[3ull * ACT_ELEMS];
__device__ __align__(16) __nv_bfloat16 g_wh[4ull * W_ELEMS];
__device__ __align__(16) __nv_bfloat16 g_wl[4ull * W_ELEMS];

// ---------------------------------------------------------------------------
// PTX helpers (compute_103-safe: no tcgen05 / no 'a'-features)
// ---------------------------------------------------------------------------
__device__ __forceinline__ uint32_t smem_u32(const void* p) {
    uint32_t a;
    asm("{ .reg .u64 t; cvta.to.shared.u64 t, %1; cvt.u32.u64 %0, t; }"
        : "=r"(a) : "l"(p));
    return a;
}

#define CP16(dst, src) \
    asm volatile("cp.async.cg.shared.global [%0], [%1], 16;" \
        :: "r"(dst), "l"(src) : "memory")
#define CP_COMMIT() asm volatile("cp.async.commit_group;" ::: "memory")
#define CP_WAIT1()  asm volatile("cp.async.wait_group 1;" ::: "memory")
#define CP_WAIT0()  asm volatile("cp.async.wait_group 0;" ::: "memory")

__device__ __forceinline__ void ldsm_x4(uint32_t* r, uint32_t addr) {
    asm volatile("ldmatrix.sync.aligned.m8n8.x4.shared.b16 {%0,%1,%2,%3}, [%4];"
        : "=r"(r[0]), "=r"(r[1]), "=r"(r[2]), "=r"(r[3]) : "r"(addr));
}

__device__ __forceinline__ void mma16816(float* c, const uint32_t* a,
                                         const uint32_t* b) {
    asm volatile(
        "mma.sync.aligned.m16n8k16.row.col.f32.bf16.bf16.f32 "
        "{%0,%1,%2,%3}, {%4,%5,%6,%7}, {%8,%9}, {%0,%1,%2,%3};"
        : "+f"(c[0]), "+f"(c[1]), "+f"(c[2]), "+f"(c[3])
        : "r"(a[0]), "r"(a[1]), "r"(a[2]), "r"(a[3]), "r"(b[0]), "r"(b[1]));
}

// ---------------------------------------------------------------------------
// Conversions
// ---------------------------------------------------------------------------
// fp32 activations [4096,1024] -> plain row-major bf16 hi/lo
__global__ __launch_bounds__(256) void conv_act(
    const float* __restrict__ X, __nv_bfloat16* __restrict__ hi,
    __nv_bfloat16* __restrict__ lo)
{
    int e = (blockIdx.x * 256 + threadIdx.x) * 4;
    float4 x = *(const float4*)(X + e);
    float xs[4] = {x.x, x.y, x.z, x.w};
    union { __nv_bfloat16 b[4]; uint2 u; } ph, pl;
    #pragma unroll
    for (int j = 0; j < 4; j++) {
        __nv_bfloat16 h = __float2bfloat16(xs[j]);
        ph.b[j] = h;
        pl.b[j] = __float2bfloat16(xs[j] - __bfloat162float(h));
    }
    *(uint2*)(hi + e) = ph.u;
    *(uint2*)(lo + e) = pl.u;
}

// fp32 W [K,N] -> transposed bf16 hi/lo Wt [N][K] row-major
__global__ void conv_wt(const float* __restrict__ W,
                        __nv_bfloat16* __restrict__ hi,
                        __nv_bfloat16* __restrict__ lo)
{
    __shared__ float t[32][33];
    int n0 = blockIdx.x * 32, k0 = blockIdx.y * 32;
    int tx = threadIdx.x, ty = threadIdx.y;  // 32 x 8

    #pragma unroll
    for (int j = 0; j < 32; j += 8)
        t[ty + j][tx] = W[(size_t)(k0 + ty + j) * 1024 + n0 + tx];
    __syncthreads();

    #pragma unroll
    for (int j = 0; j < 32; j += 8) {
        int n = n0 + ty + j, k = k0 + tx;
        float x = t[tx][ty + j];
        __nv_bfloat16 h = __float2bfloat16(x);
        __nv_bfloat16 l = __float2bfloat16(x - __bfloat162float(h));
        hi[(size_t)n * 1024 + k] = h;
        lo[(size_t)n * 1024 + k] = l;
    }
}

// ---------------------------------------------------------------------------
// HMMA GEMM: C[4096,1024] = (A @ W + bias)*scale with bf16 hi/lo split.
// CTA 128x128, BK=32, 2-stage cp.async pipeline, mma.sync m16n8k16.
// smem rows padded to 80B (5x16B banks -> ldmatrix conflict-free).
// ---------------------------------------------------------------------------
#define ROWB 80
#define ARR_B (128 * ROWB)      // 10240 per array
#define STAGE_B (4 * ARR_B)     // 40960 per stage
#define GEMM_SMEM (2 * STAGE_B) // 81920

__device__ __forceinline__ void gemm_load_stage(
    uint32_t dbase, int m0, int n0, int k0, int tid,
    const __nv_bfloat16* Ah, const __nv_bfloat16* Al,
    const __nv_bfloat16* Bh, const __nv_bfloat16* Bl)
{
    int ldc = tid & 3;       // 16B chunk within 32 k-elems
    int r0 = tid >> 2;       // rows 0..63 (+64 second half)
    #pragma unroll
    for (int h = 0; h < 2; h++) {
        int row = r0 + h * 64;
        uint32_t doff = dbase + row * ROWB + ldc * 16;
        size_t ga = (size_t)(m0 + row) * 1024 + k0 + ldc * 8;
        size_t gb = (size_t)(n0 + row) * 1024 + k0 + ldc * 8;
        CP16(doff,             Ah + ga);
        CP16(doff + ARR_B,     Al + ga);
        CP16(doff + 2 * ARR_B, Bh + gb);
        CP16(doff + 3 * ARR_B, Bl + gb);
    }
}

__global__ __launch_bounds__(256, 2) void mma_gemm(
    const __nv_bfloat16* __restrict__ Ah, const __nv_bfloat16* __restrict__ Al,
    const __nv_bfloat16* __restrict__ Bh, const __nv_bfloat16* __restrict__ Bl,
    const float* __restrict__ bias, float* __restrict__ C, float scale)
{
    extern __shared__ __align__(16) char sm[];
    const uint32_t sb = smem_u32(sm);
    const int tid = threadIdx.x;
    const int lid = tid & 31, wid = tid >> 5;
    const int wm = wid >> 1, wn = wid & 1;        // 4 x 2 warp grid
    const int m0 = blockIdx.y * 128, n0 = blockIdx.x * 128;

    float acc[2][8][4];
    #pragma unroll
    for (int f = 0; f < 2; f++)
        #pragma unroll
        for (int n = 0; n < 8; n++)
            #pragma unroll
            for (int j = 0; j < 4; j++) acc[f][n][j] = 0.0f;

    // lane-relative ldmatrix offsets
    const uint32_t a_rel = (uint32_t)(wm * 32 + (lid & 15)) * ROWB + ((lid >> 4) << 4);
    const uint32_t b_rel = (uint32_t)(wn * 64 + (lid & 7) + ((lid >> 4) << 3)) * ROWB
                           + (((lid >> 3) & 1) << 4);

    gemm_load_stage(sb, m0, n0, 0, tid, Ah, Al, Bh, Bl);
    CP_COMMIT();

    for (int c = 0; c < 32; c++) {
        const int s = c & 1;
        if (c < 31) {
            gemm_load_stage(sb + (s ^ 1) * STAGE_B, m0, n0, (c + 1) * 32, tid,
                            Ah, Al, Bh, Bl);
            CP_COMMIT();
            CP_WAIT1();
        } else {
            CP_WAIT0();
        }
        __syncthreads();

        const uint32_t base = sb + s * STAGE_B;
        #pragma unroll
        for (int ks = 0; ks < 2; ks++) {
            const uint32_t koff = ks * 32;  // 16 bf16 = 32 bytes
            uint32_t ah[2][4], al[2][4];
            #pragma unroll
            for (int f = 0; f < 2; f++) {
                ldsm_x4(ah[f], base + a_rel + f * 16 * ROWB + koff);
                ldsm_x4(al[f], base + ARR_B + a_rel + f * 16 * ROWB + koff);
            }
            #pragma unroll
            for (int nfp = 0; nfp < 4; nfp++) {
                uint32_t bh[4], bl[4];
                ldsm_x4(bh, base + 2 * ARR_B + b_rel + nfp * 16 * ROWB + koff);
                ldsm_x4(bl, base + 3 * ARR_B + b_rel + nfp * 16 * ROWB + koff);
                #pragma unroll
                for (int f = 0; f < 2; f++) {
                    mma16816(acc[f][nfp * 2 + 0], ah[f], bh + 0);
                    mma16816(acc[f][nfp * 2 + 0], ah[f], bl + 0);
                    mma16816(acc[f][nfp * 2 + 0], al[f], bh + 0);
                    mma16816(acc[f][nfp * 2 + 1], ah[f], bh + 2);
                    mma16816(acc[f][nfp * 2 + 1], ah[f], bl + 2);
                    mma16816(acc[f][nfp * 2 + 1], al[f], bh + 2);
                }
            }
        }
        __syncthreads();
    }

    // Epilogue: acc -> (acc + bias) * scale -> C
    const int r_base = m0 + wm * 32 + (lid >> 2);
    const int c_lane = (lid & 3) * 2;
    #pragma unroll
    for (int f = 0; f < 2; f++) {
        #pragma unroll
        for (int nf = 0; nf < 8; nf++) {
            int col = n0 + wn * 64 + nf * 8 + c_lane;
            float2 bb = *(const float2*)(bias + col);
            int r0 = r_base + f * 16;
            float* a = acc[f][nf];
            float2 o0 = make_float2((a[0] + bb.x) * scale, (a[1] + bb.y) * scale);
            float2 o1 = make_float2((a[2] + bb.x) * scale, (a[3] + bb.y) * scale);
            *(float2*)(C + (size_t)r0 * 1024 + col) = o0;
            *(float2*)(C + (size_t)(r0 + 8) * 1024 + col) = o1;
        }
    }
}

// ---------------------------------------------------------------------------
// Attention: flash-style, 64x64 tiles, 128 threads, 8x4 micro-tiles.
// ---------------------------------------------------------------------------
#define QS_STRIDE 68
#define KS_STRIDE 65
#define VS_STRIDE 68
#define PS_STRIDE 68
#define ATTN_SMEM ((64 * (QS_STRIDE + KS_STRIDE + VS_STRIDE + PS_STRIDE)) * 4)

__global__ __launch_bounds__(128) void attn_kernel(const float* __restrict__ bias)
{
    extern __shared__ float sh[];
    float* Qs = sh;
    float* Ks = Qs + 64 * QS_STRIDE;
    float* Vs = Ks + 64 * KS_STRIDE;
    float* Ps = Vs + 64 * VS_STRIDE;

    const int qt = blockIdx.x;
    const int h  = blockIdx.y;
    const int b  = blockIdx.z;
    const int tid = threadIdx.x;
    const int tx = tid & 15;   // key-col group (4 wide)
    const int ty = tid >> 4;   // 0..7, query-row group (8 wide)

    const float* Qg = g_q + ((size_t)(b * NN + qt * 64)) * DM + h * DK;
    #pragma unroll
    for (int t = 0; t < 8; t++) {
        int idx = tid + (t << 7);
        int r = idx >> 4;
        int c = (idx & 15) << 2;
        *(float4*)&Qs[r * QS_STRIDE + c] = *(const float4*)(Qg + (size_t)r * DM + c);
    }

    float m_r[8], l_r[8], acc[8][4];
    #pragma unroll
    for (int i = 0; i < 8; i++) {
        m_r[i] = -1e30f;
        l_r[i] = 0.0f;
        #pragma unroll
        for (int j = 0; j < 4; j++) acc[i][j] = 0.0f;
    }

    const float* biasg = bias + (((size_t)(b * NH + h)) * NN + qt * 64) * NN;

    for (int kt = 0; kt < 16; kt++) {
        __syncthreads();
        const float* Kg = g_k + ((size_t)(b * NN + kt * 64)) * DM + h * DK;
        const float* Vg = g_v + ((size_t)(b * NN + kt * 64)) * DM + h * DK;
        #pragma unroll
        for (int t = 0; t < 8; t++) {
            int idx = tid + (t << 7);
            int r = idx >> 4;
            int c = (idx & 15) << 2;
            float4 kv = *(const float4*)(Kg + (size_t)r * DM + c);
            Ks[r * KS_STRIDE + c + 0] = kv.x;
            Ks[r * KS_STRIDE + c + 1] = kv.y;
            Ks[r * KS_STRIDE + c + 2] = kv.z;
            Ks[r * KS_STRIDE + c + 3] = kv.w;
            *(float4*)&Vs[r * VS_STRIDE + c] = *(const float4*)(Vg + (size_t)r * DM + c);
        }
        __syncthreads();

        float s[8][4];
        #pragma unroll
        for (int i = 0; i < 8; i++)
            #pragma unroll
            for (int j = 0; j < 4; j++) s[i][j] = 0.0f;

        #pragma unroll 4
        for (int d = 0; d < 64; d++) {
            float a[8], kk[4];
            #pragma unroll
            for (int i = 0; i < 8; i++) a[i] = Qs[(ty * 8 + i) * QS_STRIDE + d];
            #pragma unroll
            for (int j = 0; j < 4; j++) kk[j] = Ks[(tx * 4 + j) * KS_STRIDE + d];
            #pragma unroll
            for (int i = 0; i < 8; i++)
                #pragma unroll
                for (int j = 0; j < 4; j++)
                    s[i][j] = fmaf(a[i], kk[j], s[i][j]);
        }

        #pragma unroll
        for (int i = 0; i < 8; i++) {
            float4 bb = *(const float4*)(biasg + (size_t)(ty * 8 + i) * NN + kt * 64 + (tx << 2));
            s[i][0] += bb.x; s[i][1] += bb.y; s[i][2] += bb.z; s[i][3] += bb.w;

            float tmax = fmaxf(fmaxf(s[i][0], s[i][1]), fmaxf(s[i][2], s[i][3]));
            #pragma unroll
            for (int o = 8; o >= 1; o >>= 1)
                tmax = fmaxf(tmax, __shfl_xor_sync(0xffffffffu, tmax, o));

            float mnew = fmaxf(m_r[i], tmax);
            float sc = __expf(m_r[i] - mnew);
            float rs = 0.0f;
            #pragma unroll
            for (int j = 0; j < 4; j++) {
                s[i][j] = __expf(s[i][j] - mnew);
                rs += s[i][j];
            }
            #pragma unroll
            for (int o = 8; o >= 1; o >>= 1)
                rs += __shfl_xor_sync(0xffffffffu, rs, o);

            l_r[i] = l_r[i] * sc + rs;
            m_r[i] = mnew;
            #pragma unroll
            for (int j = 0; j < 4; j++) acc[i][j] *= sc;

            *(float4*)&Ps[(ty * 8 + i) * PS_STRIDE + (tx << 2)] =
                make_float4(s[i][0], s[i][1], s[i][2], s[i][3]);
        }
        __syncthreads();

        #pragma unroll 4
        for (int k = 0; k < 64; k++) {
            float p[8];
            #pragma unroll
            for (int i = 0; i < 8; i++) p[i] = Ps[(ty * 8 + i) * PS_STRIDE + k];
            float4 vv = *(float4*)&Vs[k * VS_STRIDE + (tx << 2)];
            float v4[4] = {vv.x, vv.y, vv.z, vv.w};
            #pragma unroll
            for (int i = 0; i < 8; i++)
                #pragma unroll
                for (int j = 0; j < 4; j++)
                    acc[i][j] = fmaf(p[i], v4[j], acc[i][j]);
        }
    }

    float* Og = g_ctx + ((size_t)(b * NN + qt * 64)) * DM + h * DK;
    #pragma unroll
    for (int i = 0; i < 8; i++) {
        float inv = 1.0f / l_r[i];
        float4 o = make_float4(acc[i][0] * inv, acc[i][1] * inv,
                               acc[i][2] * inv, acc[i][3] * inv);
        *(float4*)(Og + (size_t)(ty * 8 + i) * DM + (tx << 2)) = o;
    }
}

// ---------------------------------------------------------------------------
// Launch
// ---------------------------------------------------------------------------
extern "C" void kernel_launch(void* const* d_in, const int* in_sizes, int n_in,
                              void* d_out, int out_size)
{
    const float* queries   = (const float*)d_in[0];
    const float* keys      = (const float*)d_in[1];
    const float* values    = (const float*)d_in[2];
    const float* attn_bias = (const float*)d_in[3];
    const float* Wq = (const float*)d_in[4];
    const float* bq = (const float*)d_in[5];
    const float* Wk = (const float*)d_in[6];
    const float* bk = (const float*)d_in[7];
    const float* Wv = (const float*)d_in[8];
    const float* bv = (const float*)d_in[9];
    const float* Wo = (const float*)d_in[10];
    const float* bo = (const float*)d_in[11];
    float* out = (float*)d_out;

    float *q, *k, *v, *ctx;
    cudaGetSymbolAddress((void**)&q,   g_q);
    cudaGetSymbolAddress((void**)&k,   g_k);
    cudaGetSymbolAddress((void**)&v,   g_v);
    cudaGetSymbolAddress((void**)&ctx, g_ctx);
    __nv_bfloat16 *ah, *al, *wh, *wl;
    cudaGetSymbolAddress((void**)&ah, g_ah);
    cudaGetSymbolAddress((void**)&al, g_al);
    cudaGetSymbolAddress((void**)&wh, g_wh);
    cudaGetSymbolAddress((void**)&wl, g_wl);

    cudaFuncSetAttribute(attn_kernel,
                         cudaFuncAttributeMaxDynamicSharedMemorySize, ATTN_SMEM);
    cudaFuncSetAttribute(mma_gemm,
                         cudaFuncAttributeMaxDynamicSharedMemorySize, GEMM_SMEM);

    dim3 cwt_grid(32, 32), cwt_blk(32, 8);
    dim3 gemm_grid(8, 32);  // (N/128, M/128)

    conv_act<<<4096, 256>>>(queries, ah + 0ull * ACT_ELEMS, al + 0ull * ACT_ELEMS);
    conv_act<<<4096, 256>>>(keys,    ah + 1ull * ACT_ELEMS, al + 1ull * ACT_ELEMS);
    conv_act<<<4096, 256>>>(values,  ah + 2ull * ACT_ELEMS, al + 2ull * ACT_ELEMS);
    conv_wt<<<cwt_grid, cwt_blk>>>(Wq, wh + 0ull * W_ELEMS, wl + 0ull * W_ELEMS);
    conv_wt<<<cwt_grid, cwt_blk>>>(Wk, wh + 1ull * W_ELEMS, wl + 1ull * W_ELEMS);
    conv_wt<<<cwt_grid, cwt_blk>>>(Wv, wh + 2ull * W_ELEMS, wl + 2ull * W_ELEMS);
    conv_wt<<<cwt_grid, cwt_blk>>>(Wo, wh + 3ull * W_ELEMS, wl + 3ull * W_ELEMS);

    mma_gemm<<<gemm_grid, 256, GEMM_SMEM>>>(ah + 0ull * ACT_ELEMS, al + 0ull * ACT_ELEMS,
                                            wh + 0ull * W_ELEMS, wl + 0ull * W_ELEMS,
                                            bq, q, 0.125f);
    mma_gemm<<<gemm_grid, 256, GEMM_SMEM>>>(ah + 1ull * ACT_ELEMS, al + 1ull * ACT_ELEMS,
                                            wh + 1ull * W_ELEMS, wl + 1ull * W_ELEMS,
                                            bk, k, 1.0f);
    mma_gemm<<<gemm_grid, 256, GEMM_SMEM>>>(ah + 2ull * ACT_ELEMS, al + 2ull * ACT_ELEMS,
                                            wh + 2ull * W_ELEMS, wl + 2ull * W_ELEMS,
                                            bv, v, 1.0f);

    attn_kernel<<<dim3(16, 16, 4), 128, ATTN_SMEM>>>(attn_bias);

    conv_act<<<4096, 256>>>(ctx, ah + 0ull * ACT_ELEMS, al + 0ull * ACT_ELEMS);
    mma_gemm<<<gemm_grid, 256, GEMM_SMEM>>>(ah + 0ull * ACT_ELEMS, al + 0ull * ACT_ELEMS,
                                            wh + 3ull * W_ELEMS, wl + 3ull * W_ELEMS,
                                            bo, out, 1.0f);
}

// round 4
// speedup vs baseline: 2.0962x; 1.2927x over previous
#include <cuda_runtime.h>
#include <cuda_bf16.h>
#include <math.h>
#include <stdint.h>

// Problem constants
#define BB 4
#define NN 1024
#define DM 1024
#define NH 16
#define DK 64

// ---------------------------------------------------------------------------
// Scratch (__device__ globals; allocation-free rule)
// ---------------------------------------------------------------------------
#define ACT_ELEMS (4096 * 1024)
#define W_ELEMS   (1024 * 1024)
__device__ __align__(16) __nv_bfloat16 g_ah[3ull * ACT_ELEMS];
__device__ __align__(16) __nv_bfloat16 g_al[3ull * ACT_ELEMS];
__device__ __align__(16) __nv_bfloat16 g_wh[4ull * W_ELEMS];
__device__ __align__(16) __nv_bfloat16 g_wl[4ull * W_ELEMS];
// q/k/v projections and ctx, bf16 hi/lo, [4096,1024] row-major
__device__ __align__(16) __nv_bfloat16 g_qh[ACT_ELEMS], g_ql[ACT_ELEMS];
__device__ __align__(16) __nv_bfloat16 g_kh[ACT_ELEMS], g_kl[ACT_ELEMS];
__device__ __align__(16) __nv_bfloat16 g_vh[ACT_ELEMS], g_vl[ACT_ELEMS];
__device__ __align__(16) __nv_bfloat16 g_ch[ACT_ELEMS], g_cl[ACT_ELEMS];

// ---------------------------------------------------------------------------
// PTX helpers (compute_103-safe)
// ---------------------------------------------------------------------------
__device__ __forceinline__ uint32_t smem_u32(const void* p) {
    uint32_t a;
    asm("{ .reg .u64 t; cvta.to.shared.u64 t, %1; cvt.u32.u64 %0, t; }"
        : "=r"(a) : "l"(p));
    return a;
}

#define CP16(dst, src) \
    asm volatile("cp.async.cg.shared.global [%0], [%1], 16;" \
        :: "r"(dst), "l"(src) : "memory")
#define CP_COMMIT() asm volatile("cp.async.commit_group;" ::: "memory")
#define CP_WAIT1()  asm volatile("cp.async.wait_group 1;" ::: "memory")
#define CP_WAIT0()  asm volatile("cp.async.wait_group 0;" ::: "memory")

__device__ __forceinline__ void ldsm_x4(uint32_t* r, uint32_t addr) {
    asm volatile("ldmatrix.sync.aligned.m8n8.x4.shared.b16 {%0,%1,%2,%3}, [%4];"
        : "=r"(r[0]), "=r"(r[1]), "=r"(r[2]), "=r"(r[3]) : "r"(addr));
}
__device__ __forceinline__ void ldsm_x4_t(uint32_t* r, uint32_t addr) {
    asm volatile("ldmatrix.sync.aligned.m8n8.x4.trans.shared.b16 {%0,%1,%2,%3}, [%4];"
        : "=r"(r[0]), "=r"(r[1]), "=r"(r[2]), "=r"(r[3]) : "r"(addr));
}

__device__ __forceinline__ void mma16816(float* c, const uint32_t* a,
                                         const uint32_t* b) {
    asm volatile(
        "mma.sync.aligned.m16n8k16.row.col.f32.bf16.bf16.f32 "
        "{%0,%1,%2,%3}, {%4,%5,%6,%7}, {%8,%9}, {%0,%1,%2,%3};"
        : "+f"(c[0]), "+f"(c[1]), "+f"(c[2]), "+f"(c[3])
        : "r"(a[0]), "r"(a[1]), "r"(a[2]), "r"(a[3]), "r"(b[0]), "r"(b[1]));
}

// split a float pair into packed bf16x2 hi + lo
__device__ __forceinline__ void split2(float x, float y, uint32_t& h, uint32_t& l) {
    __nv_bfloat16 hx = __float2bfloat16(x), hy = __float2bfloat16(y);
    __nv_bfloat16 lx = __float2bfloat16(x - __bfloat162float(hx));
    __nv_bfloat16 ly = __float2bfloat16(y - __bfloat162float(hy));
    __nv_bfloat162 th(hx, hy), tl(lx, ly);
    h = *(uint32_t*)&th;
    l = *(uint32_t*)&tl;
}

// ---------------------------------------------------------------------------
// Conversions (inputs only)
// ---------------------------------------------------------------------------
__global__ __launch_bounds__(256) void conv_act(
    const float* __restrict__ X, __nv_bfloat16* __restrict__ hi,
    __nv_bfloat16* __restrict__ lo)
{
    int e = (blockIdx.x * 256 + threadIdx.x) * 4;
    float4 x = *(const float4*)(X + e);
    float xs[4] = {x.x, x.y, x.z, x.w};
    union { __nv_bfloat16 b[4]; uint2 u; } ph, pl;
    #pragma unroll
    for (int j = 0; j < 4; j++) {
        __nv_bfloat16 h = __float2bfloat16(xs[j]);
        ph.b[j] = h;
        pl.b[j] = __float2bfloat16(xs[j] - __bfloat162float(h));
    }
    *(uint2*)(hi + e) = ph.u;
    *(uint2*)(lo + e) = pl.u;
}

__global__ void conv_wt(const float* __restrict__ W,
                        __nv_bfloat16* __restrict__ hi,
                        __nv_bfloat16* __restrict__ lo)
{
    __shared__ float t[32][33];
    int n0 = blockIdx.x * 32, k0 = blockIdx.y * 32;
    int tx = threadIdx.x, ty = threadIdx.y;  // 32 x 8

    #pragma unroll
    for (int j = 0; j < 32; j += 8)
        t[ty + j][tx] = W[(size_t)(k0 + ty + j) * 1024 + n0 + tx];
    __syncthreads();

    #pragma unroll
    for (int j = 0; j < 32; j += 8) {
        int n = n0 + ty + j, k = k0 + tx;
        float x = t[tx][ty + j];
        __nv_bfloat16 h = __float2bfloat16(x);
        __nv_bfloat16 l = __float2bfloat16(x - __bfloat162float(h));
        hi[(size_t)n * 1024 + k] = h;
        lo[(size_t)n * 1024 + k] = l;
    }
}

// ---------------------------------------------------------------------------
// HMMA GEMM, bf16 hi/lo split; optionally emits bf16 hi/lo output.
// ---------------------------------------------------------------------------
#define ROWB 80
#define ARR_B (128 * ROWB)
#define STAGE_B (4 * ARR_B)
#define GEMM_SMEM (2 * STAGE_B)

__device__ __forceinline__ void gemm_load_stage(
    uint32_t dbase, int m0, int n0, int k0, int tid,
    const __nv_bfloat16* Ah, const __nv_bfloat16* Al,
    const __nv_bfloat16* Bh, const __nv_bfloat16* Bl)
{
    int ldc = tid & 3;
    int r0 = tid >> 2;
    #pragma unroll
    for (int h = 0; h < 2; h++) {
        int row = r0 + h * 64;
        uint32_t doff = dbase + row * ROWB + ldc * 16;
        size_t ga = (size_t)(m0 + row) * 1024 + k0 + ldc * 8;
        size_t gb = (size_t)(n0 + row) * 1024 + k0 + ldc * 8;
        CP16(doff,             Ah + ga);
        CP16(doff + ARR_B,     Al + ga);
        CP16(doff + 2 * ARR_B, Bh + gb);
        CP16(doff + 3 * ARR_B, Bl + gb);
    }
}

template <bool OUT_BF16>
__global__ __launch_bounds__(256, 2) void mma_gemm(
    const __nv_bfloat16* __restrict__ Ah, const __nv_bfloat16* __restrict__ Al,
    const __nv_bfloat16* __restrict__ Bh, const __nv_bfloat16* __restrict__ Bl,
    const float* __restrict__ bias, float* __restrict__ C,
    __nv_bfloat16* __restrict__ Ch, __nv_bfloat16* __restrict__ Cl, float scale)
{
    extern __shared__ __align__(16) char sm[];
    const uint32_t sb = smem_u32(sm);
    const int tid = threadIdx.x;
    const int lid = tid & 31, wid = tid >> 5;
    const int wm = wid >> 1, wn = wid & 1;
    const int m0 = blockIdx.y * 128, n0 = blockIdx.x * 128;

    float acc[2][8][4];
    #pragma unroll
    for (int f = 0; f < 2; f++)
        #pragma unroll
        for (int n = 0; n < 8; n++)
            #pragma unroll
            for (int j = 0; j < 4; j++) acc[f][n][j] = 0.0f;

    const uint32_t a_rel = (uint32_t)(wm * 32 + (lid & 15)) * ROWB + ((lid >> 4) << 4);
    const uint32_t b_rel = (uint32_t)(wn * 64 + (lid & 7) + ((lid >> 4) << 3)) * ROWB
                           + (((lid >> 3) & 1) << 4);

    gemm_load_stage(sb, m0, n0, 0, tid, Ah, Al, Bh, Bl);
    CP_COMMIT();

    for (int c = 0; c < 32; c++) {
        const int s = c & 1;
        if (c < 31) {
            gemm_load_stage(sb + (s ^ 1) * STAGE_B, m0, n0, (c + 1) * 32, tid,
                            Ah, Al, Bh, Bl);
            CP_COMMIT();
            CP_WAIT1();
        } else {
            CP_WAIT0();
        }
        __syncthreads();

        const uint32_t base = sb + s * STAGE_B;
        #pragma unroll
        for (int ks = 0; ks < 2; ks++) {
            const uint32_t koff = ks * 32;
            uint32_t ah[2][4], al[2][4];
            #pragma unroll
            for (int f = 0; f < 2; f++) {
                ldsm_x4(ah[f], base + a_rel + f * 16 * ROWB + koff);
                ldsm_x4(al[f], base + ARR_B + a_rel + f * 16 * ROWB + koff);
            }
            #pragma unroll
            for (int nfp = 0; nfp < 4; nfp++) {
                uint32_t bh[4], bl[4];
                ldsm_x4(bh, base + 2 * ARR_B + b_rel + nfp * 16 * ROWB + koff);
                ldsm_x4(bl, base + 3 * ARR_B + b_rel + nfp * 16 * ROWB + koff);
                #pragma unroll
                for (int f = 0; f < 2; f++) {
                    mma16816(acc[f][nfp * 2 + 0], ah[f], bh + 0);
                    mma16816(acc[f][nfp * 2 + 0], ah[f], bl + 0);
                    mma16816(acc[f][nfp * 2 + 0], al[f], bh + 0);
                    mma16816(acc[f][nfp * 2 + 1], ah[f], bh + 2);
                    mma16816(acc[f][nfp * 2 + 1], ah[f], bl + 2);
                    mma16816(acc[f][nfp * 2 + 1], al[f], bh + 2);
                }
            }
        }
        __syncthreads();
    }

    const int r_base = m0 + wm * 32 + (lid >> 2);
    const int c_lane = (lid & 3) * 2;
    #pragma unroll
    for (int f = 0; f < 2; f++) {
        #pragma unroll
        for (int nf = 0; nf < 8; nf++) {
            int col = n0 + wn * 64 + nf * 8 + c_lane;
            float2 bb = *(const float2*)(bias + col);
            int r0 = r_base + f * 16;
            float* a = acc[f][nf];
            float v0 = (a[0] + bb.x) * scale, v1 = (a[1] + bb.y) * scale;
            float v2 = (a[2] + bb.x) * scale, v3 = (a[3] + bb.y) * scale;
            if (OUT_BF16) {
                uint32_t h0, l0, h1, l1;
                split2(v0, v1, h0, l0);
                split2(v2, v3, h1, l1);
                *(uint32_t*)(Ch + (size_t)r0 * 1024 + col) = h0;
                *(uint32_t*)(Cl + (size_t)r0 * 1024 + col) = l0;
                *(uint32_t*)(Ch + (size_t)(r0 + 8) * 1024 + col) = h1;
                *(uint32_t*)(Cl + (size_t)(r0 + 8) * 1024 + col) = l1;
            } else {
                *(float2*)(C + (size_t)r0 * 1024 + col) = make_float2(v0, v1);
                *(float2*)(C + (size_t)(r0 + 8) * 1024 + col) = make_float2(v2, v3);
            }
        }
    }
}

// ---------------------------------------------------------------------------
// Tensor-core flash attention, bf16 hi/lo split both stages.
// CTA: 128 threads (4 warps), Q tile 64 rows; 16 key tiles of 64.
// ---------------------------------------------------------------------------
#define KROWB 144                    // 64 bf16 (128B) + 16B pad
#define TILE9K (64 * KROWB)          // 9216
#define BROWB 288                    // 64 fp32 (256B) + 32B pad
#define BIAS_B (64 * BROWB)          // 18432
#define STAGE_A (4 * TILE9K + BIAS_B)  // 55296: Kh,Kl,Vh,Vl,bias
#define Q_OFF (2 * STAGE_A)
#define ATTN_SMEM (Q_OFF + 2 * TILE9K)  // 129024

__device__ __forceinline__ void attn_load_stage(
    uint32_t dst, const char* smbase_unused, int b, int h, int qt, int kt, int tid,
    const float* __restrict__ bias,
    const __nv_bfloat16* __restrict__ kh, const __nv_bfloat16* __restrict__ kl,
    const __nv_bfloat16* __restrict__ vh, const __nv_bfloat16* __restrict__ vl)
{
    const size_t krow = (size_t)(b * NN + kt * 64);
    #pragma unroll
    for (int t = 0; t < 4; t++) {
        int chunk = tid + t * 128;
        int r = chunk >> 3, c = chunk & 7;
        size_t g = (krow + r) * DM + h * 64 + c * 8;
        uint32_t d = dst + r * KROWB + c * 16;
        CP16(d,              kh + g);
        CP16(d + TILE9K,     kl + g);
        CP16(d + 2 * TILE9K, vh + g);
        CP16(d + 3 * TILE9K, vl + g);
    }
    const float* bg = bias + (((size_t)(b * NH + h)) * NN + qt * 64) * NN + kt * 64;
    #pragma unroll
    for (int t = 0; t < 8; t++) {
        int chunk = tid + t * 128;
        int r = chunk >> 4, c = chunk & 15;
        CP16(dst + 4 * TILE9K + r * BROWB + c * 16, bg + (size_t)r * NN + c * 4);
    }
}

__global__ __launch_bounds__(128) void attn_mma(
    const float* __restrict__ bias,
    const __nv_bfloat16* __restrict__ qh, const __nv_bfloat16* __restrict__ ql,
    const __nv_bfloat16* __restrict__ kh, const __nv_bfloat16* __restrict__ kl,
    const __nv_bfloat16* __restrict__ vh, const __nv_bfloat16* __restrict__ vl,
    __nv_bfloat16* __restrict__ ch, __nv_bfloat16* __restrict__ cl)
{
    extern __shared__ __align__(16) char sm[];
    const uint32_t sb = smem_u32(sm);
    const int tid = threadIdx.x, lid = tid & 31, wid = tid >> 5;
    const int bh = blockIdx.x;             // b*16 + h (fast dim -> K/V L2 reuse)
    const int qt = blockIdx.y;
    const int b = bh >> 4, h = bh & 15;
    const size_t qrow0 = (size_t)(b * NN + qt * 64);

    // Q tile (hi/lo) -> smem, plus stage 0 and stage 1 prefetch
    #pragma unroll
    for (int t = 0; t < 4; t++) {
        int chunk = tid + t * 128;
        int r = chunk >> 3, c = chunk & 7;
        size_t g = (qrow0 + r) * DM + h * 64 + c * 8;
        CP16(sb + Q_OFF + r * KROWB + c * 16, qh + g);
        CP16(sb + Q_OFF + TILE9K + r * KROWB + c * 16, ql + g);
    }
    attn_load_stage(sb, sm, b, h, qt, 0, tid, bias, kh, kl, vh, vl);
    CP_COMMIT();
    attn_load_stage(sb + STAGE_A, sm, b, h, qt, 1, tid, bias, kh, kl, vh, vl);
    CP_COMMIT();
    CP_WAIT1();   // Q + stage0 complete
    __syncthreads();

    // Q fragments (registers, reused across all 16 key tiles)
    uint32_t aqh[4][4], aql[4][4];
    {
        const uint32_t qrel = sb + Q_OFF + (uint32_t)(wid * 16 + (lid & 15)) * KROWB
                              + ((lid >> 4) << 4);
        #pragma unroll
        for (int ks = 0; ks < 4; ks++) {
            ldsm_x4(aqh[ks], qrel + ks * 32);
            ldsm_x4(aql[ks], qrel + TILE9K + ks * 32);
        }
    }

    float o[8][4];
    #pragma unroll
    for (int j = 0; j < 8; j++)
        #pragma unroll
        for (int e = 0; e < 4; e++) o[j][e] = 0.0f;
    float m0 = -1e30f, m1 = -1e30f, l0 = 0.0f, l1 = 0.0f;

    const int rrow = (lid >> 2);           // 0..7 within warp tile
    const uint32_t krel_lane = (uint32_t)((lid & 7) + ((lid >> 4) << 3)) * KROWB
                               + (((lid >> 3) & 1) << 4);
    const uint32_t vcol_lane = ((lid >> 4) << 4);
    const uint32_t vrow_lane = (uint32_t)(lid & 15) * KROWB;

    for (int kt = 0; kt < 16; kt++) {
        const uint32_t st = sb + (kt & 1) * STAGE_A;
        const uint32_t strel = (kt & 1) * STAGE_A;

        // ---- S = Q K^T (hi/lo split) ----
        float s[8][4];
        #pragma unroll
        for (int j = 0; j < 8; j++)
            #pragma unroll
            for (int e = 0; e < 4; e++) s[j][e] = 0.0f;

        #pragma unroll
        for (int ks = 0; ks < 4; ks++) {
            const uint32_t kbase = st + krel_lane + ks * 32;
            #pragma unroll
            for (int np = 0; np < 4; np++) {
                uint32_t bkh[4], bkl[4];
                ldsm_x4(bkh, kbase + np * 16 * KROWB);
                ldsm_x4(bkl, kbase + TILE9K + np * 16 * KROWB);
                mma16816(s[2 * np + 0], aqh[ks], bkh + 0);
                mma16816(s[2 * np + 0], aqh[ks], bkl + 0);
                mma16816(s[2 * np + 0], aql[ks], bkh + 0);
                mma16816(s[2 * np + 1], aqh[ks], bkh + 2);
                mma16816(s[2 * np + 1], aqh[ks], bkl + 2);
                mma16816(s[2 * np + 1], aql[ks], bkh + 2);
            }
        }

        // ---- + bias (from smem stage) ----
        {
            const char* bsm = sm + strel + 4 * TILE9K
                              + (wid * 16 + rrow) * BROWB + (lid & 3) * 8;
            #pragma unroll
            for (int j = 0; j < 8; j++) {
                float2 b0 = *(const float2*)(bsm + j * 32);
                float2 b1 = *(const float2*)(bsm + 8 * BROWB + j * 32);
                s[j][0] += b0.x; s[j][1] += b0.y;
                s[j][2] += b1.x; s[j][3] += b1.y;
            }
        }

        // ---- online softmax ----
        float mx0 = -1e30f, mx1 = -1e30f;
        #pragma unroll
        for (int j = 0; j < 8; j++) {
            mx0 = fmaxf(mx0, fmaxf(s[j][0], s[j][1]));
            mx1 = fmaxf(mx1, fmaxf(s[j][2], s[j][3]));
        }
        mx0 = fmaxf(mx0, __shfl_xor_sync(0xffffffffu, mx0, 1));
        mx0 = fmaxf(mx0, __shfl_xor_sync(0xffffffffu, mx0, 2));
        mx1 = fmaxf(mx1, __shfl_xor_sync(0xffffffffu, mx1, 1));
        mx1 = fmaxf(mx1, __shfl_xor_sync(0xffffffffu, mx1, 2));

        float mn0 = fmaxf(m0, mx0), mn1 = fmaxf(m1, mx1);
        float sc0 = __expf(m0 - mn0), sc1 = __expf(m1 - mn1);
        m0 = mn0; m1 = mn1;

        float rs0 = 0.0f, rs1 = 0.0f;
        #pragma unroll
        for (int j = 0; j < 8; j++) {
            s[j][0] = __expf(s[j][0] - m0);
            s[j][1] = __expf(s[j][1] - m0);
            s[j][2] = __expf(s[j][2] - m1);
            s[j][3] = __expf(s[j][3] - m1);
            rs0 += s[j][0] + s[j][1];
            rs1 += s[j][2] + s[j][3];
        }
        rs0 += __shfl_xor_sync(0xffffffffu, rs0, 1);
        rs0 += __shfl_xor_sync(0xffffffffu, rs0, 2);
        rs1 += __shfl_xor_sync(0xffffffffu, rs1, 1);
        rs1 += __shfl_xor_sync(0xffffffffu, rs1, 2);
        l0 = l0 * sc0 + rs0;
        l1 = l1 * sc1 + rs1;

        #pragma unroll
        for (int j = 0; j < 8; j++) {
            o[j][0] *= sc0; o[j][1] *= sc0;
            o[j][2] *= sc1; o[j][3] *= sc1;
        }

        // ---- pack P -> bf16 hi/lo A-fragments ----
        uint32_t pah[4][4], pal[4][4];
        #pragma unroll
        for (int ks = 0; ks < 4; ks++) {
            split2(s[2 * ks][0],     s[2 * ks][1],     pah[ks][0], pal[ks][0]);
            split2(s[2 * ks][2],     s[2 * ks][3],     pah[ks][1], pal[ks][1]);
            split2(s[2 * ks + 1][0], s[2 * ks + 1][1], pah[ks][2], pal[ks][2]);
            split2(s[2 * ks + 1][2], s[2 * ks + 1][3], pah[ks][3], pal[ks][3]);
        }

        // ---- O += P V (hi/lo split, V via ldmatrix.trans) ----
        #pragma unroll
        for (int ks = 0; ks < 4; ks++) {
            const uint32_t vbase = st + 2 * TILE9K + ks * 16 * KROWB
                                   + vrow_lane + vcol_lane;
            #pragma unroll
            for (int np = 0; np < 4; np++) {
                uint32_t bvh[4], bvl[4];
                ldsm_x4_t(bvh, vbase + np * 32);
                ldsm_x4_t(bvl, vbase + TILE9K + np * 32);
                mma16816(o[2 * np + 0], pah[ks], bvh + 0);
                mma16816(o[2 * np + 0], pah[ks], bvl + 0);
                mma16816(o[2 * np + 0], pal[ks], bvh + 0);
                mma16816(o[2 * np + 1], pah[ks], bvh + 2);
                mma16816(o[2 * np + 1], pah[ks], bvl + 2);
                mma16816(o[2 * np + 1], pal[ks], bvh + 2);
            }
        }

        __syncthreads();  // done with stage (kt&1)
        if (kt < 15) {
            if (kt + 2 < 16) {
                attn_load_stage(sb + ((kt & 1)) * STAGE_A, sm, b, h, qt, kt + 2,
                                tid, bias, kh, kl, vh, vl);
                CP_COMMIT();
                CP_WAIT1();
            } else {
                CP_WAIT0();
            }
            __syncthreads();
        }
    }

    // ---- epilogue: ctx = O / l -> bf16 hi/lo ----
    const float inv0 = 1.0f / l0, inv1 = 1.0f / l1;
    const size_t grow0 = qrow0 + wid * 16 + rrow;
    #pragma unroll
    for (int j = 0; j < 8; j++) {
        int col = h * 64 + j * 8 + (lid & 3) * 2;
        uint32_t h0, lo0, h1, lo1;
        split2(o[j][0] * inv0, o[j][1] * inv0, h0, lo0);
        split2(o[j][2] * inv1, o[j][3] * inv1, h1, lo1);
        *(uint32_t*)(ch + grow0 * DM + col) = h0;
        *(uint32_t*)(cl + grow0 * DM + col) = lo0;
        *(uint32_t*)(ch + (grow0 + 8) * DM + col) = h1;
        *(uint32_t*)(cl + (grow0 + 8) * DM + col) = lo1;
    }
}

// ---------------------------------------------------------------------------
// Launch
// ---------------------------------------------------------------------------
extern "C" void kernel_launch(void* const* d_in, const int* in_sizes, int n_in,
                              void* d_out, int out_size)
{
    const float* queries   = (const float*)d_in[0];
    const float* keys      = (const float*)d_in[1];
    const float* values    = (const float*)d_in[2];
    const float* attn_bias = (const float*)d_in[3];
    const float* Wq = (const float*)d_in[4];
    const float* bq = (const float*)d_in[5];
    const float* Wk = (const float*)d_in[6];
    const float* bk = (const float*)d_in[7];
    const float* Wv = (const float*)d_in[8];
    const float* bv = (const float*)d_in[9];
    const float* Wo = (const float*)d_in[10];
    const float* bo = (const float*)d_in[11];
    float* out = (float*)d_out;

    __nv_bfloat16 *ah, *al, *wh, *wl;
    __nv_bfloat16 *Qh, *Ql, *Kh, *Kl, *Vh, *Vl, *Ch, *Cl;
    cudaGetSymbolAddress((void**)&ah, g_ah);
    cudaGetSymbolAddress((void**)&al, g_al);
    cudaGetSymbolAddress((void**)&wh, g_wh);
    cudaGetSymbolAddress((void**)&wl, g_wl);
    cudaGetSymbolAddress((void**)&Qh, g_qh);
    cudaGetSymbolAddress((void**)&Ql, g_ql);
    cudaGetSymbolAddress((void**)&Kh, g_kh);
    cudaGetSymbolAddress((void**)&Kl, g_kl);
    cudaGetSymbolAddress((void**)&Vh, g_vh);
    cudaGetSymbolAddress((void**)&Vl, g_vl);
    cudaGetSymbolAddress((void**)&Ch, g_ch);
    cudaGetSymbolAddress((void**)&Cl, g_cl);

    cudaFuncSetAttribute(attn_mma,
                         cudaFuncAttributeMaxDynamicSharedMemorySize, ATTN_SMEM);
    cudaFuncSetAttribute(mma_gemm<true>,
                         cudaFuncAttributeMaxDynamicSharedMemorySize, GEMM_SMEM);
    cudaFuncSetAttribute(mma_gemm<false>,
                         cudaFuncAttributeMaxDynamicSharedMemorySize, GEMM_SMEM);

    dim3 cwt_grid(32, 32), cwt_blk(32, 8);
    dim3 gemm_grid(8, 32);  // (N/128, M/128)

    conv_act<<<4096, 256>>>(queries, ah + 0ull * ACT_ELEMS, al + 0ull * ACT_ELEMS);
    conv_act<<<4096, 256>>>(keys,    ah + 1ull * ACT_ELEMS, al + 1ull * ACT_ELEMS);
    conv_act<<<4096, 256>>>(values,  ah + 2ull * ACT_ELEMS, al + 2ull * ACT_ELEMS);
    conv_wt<<<cwt_grid, cwt_blk>>>(Wq, wh + 0ull * W_ELEMS, wl + 0ull * W_ELEMS);
    conv_wt<<<cwt_grid, cwt_blk>>>(Wk, wh + 1ull * W_ELEMS, wl + 1ull * W_ELEMS);
    conv_wt<<<cwt_grid, cwt_blk>>>(Wv, wh + 2ull * W_ELEMS, wl + 2ull * W_ELEMS);
    conv_wt<<<cwt_grid, cwt_blk>>>(Wo, wh + 3ull * W_ELEMS, wl + 3ull * W_ELEMS);

    // QKV projections -> bf16 hi/lo (Q pre-scaled by D_KEY^-0.5)
    mma_gemm<true><<<gemm_grid, 256, GEMM_SMEM>>>(
        ah + 0ull * ACT_ELEMS, al + 0ull * ACT_ELEMS,
        wh + 0ull * W_ELEMS, wl + 0ull * W_ELEMS, bq, nullptr, Qh, Ql, 0.125f);
    mma_gemm<true><<<gemm_grid, 256, GEMM_SMEM>>>(
        ah + 1ull * ACT_ELEMS, al + 1ull * ACT_ELEMS,
        wh + 1ull * W_ELEMS, wl + 1ull * W_ELEMS, bk, nullptr, Kh, Kl, 1.0f);
    mma_gemm<true><<<gemm_grid, 256, GEMM_SMEM>>>(
        ah + 2ull * ACT_ELEMS, al + 2ull * ACT_ELEMS,
        wh + 2ull * W_ELEMS, wl + 2ull * W_ELEMS, bv, nullptr, Vh, Vl, 1.0f);

    attn_mma<<<dim3(64, 16), 128, ATTN_SMEM>>>(attn_bias, Qh, Ql, Kh, Kl,
                                               Vh, Vl, Ch, Cl);

    // Output projection from bf16 hi/lo ctx -> fp32 out
    mma_gemm<false><<<gemm_grid, 256, GEMM_SMEM>>>(
        Ch, Cl, wh + 3ull * W_ELEMS, wl + 3ull * W_ELEMS, bo, out,
        nullptr, nullptr, 1.0f);
}

// round 5
// speedup vs baseline: 2.4401x; 1.1641x over previous
#include <cuda_runtime.h>
#include <cuda_bf16.h>
#include <math.h>
#include <stdint.h>

// Problem constants
#define BB 4
#define NN 1024
#define DM 1024
#define NH 16
#define DK 64

// ---------------------------------------------------------------------------
// Scratch (__device__ globals; allocation-free rule)
// ---------------------------------------------------------------------------
#define ACT_ELEMS (4096 * 1024)
#define W_ELEMS   (1024 * 1024)
__device__ __align__(16) __nv_bfloat16 g_ah[3ull * ACT_ELEMS];
__device__ __align__(16) __nv_bfloat16 g_al[3ull * ACT_ELEMS];
__device__ __align__(16) __nv_bfloat16 g_wh[4ull * W_ELEMS];
__device__ __align__(16) __nv_bfloat16 g_wl[4ull * W_ELEMS];
// q/k/v projections: slot 0=Q, 1=K, 2=V ; ctx hi/lo
__device__ __align__(16) __nv_bfloat16 g_qkvh[3ull * ACT_ELEMS];
__device__ __align__(16) __nv_bfloat16 g_qkvl[3ull * ACT_ELEMS];
__device__ __align__(16) __nv_bfloat16 g_ch[ACT_ELEMS], g_cl[ACT_ELEMS];

// ---------------------------------------------------------------------------
// PTX helpers (compute_103-safe)
// ---------------------------------------------------------------------------
__device__ __forceinline__ uint32_t smem_u32(const void* p) {
    uint32_t a;
    asm("{ .reg .u64 t; cvta.to.shared.u64 t, %1; cvt.u32.u64 %0, t; }"
        : "=r"(a) : "l"(p));
    return a;
}

#define CP16(dst, src) \
    asm volatile("cp.async.cg.shared.global [%0], [%1], 16;" \
        :: "r"(dst), "l"(src) : "memory")
#define CP_COMMIT() asm volatile("cp.async.commit_group;" ::: "memory")
#define CP_WAIT1()  asm volatile("cp.async.wait_group 1;" ::: "memory")
#define CP_WAIT0()  asm volatile("cp.async.wait_group 0;" ::: "memory")

__device__ __forceinline__ void ldsm_x4(uint32_t* r, uint32_t addr) {
    asm volatile("ldmatrix.sync.aligned.m8n8.x4.shared.b16 {%0,%1,%2,%3}, [%4];"
        : "=r"(r[0]), "=r"(r[1]), "=r"(r[2]), "=r"(r[3]) : "r"(addr));
}
__device__ __forceinline__ void ldsm_x4_t(uint32_t* r, uint32_t addr) {
    asm volatile("ldmatrix.sync.aligned.m8n8.x4.trans.shared.b16 {%0,%1,%2,%3}, [%4];"
        : "=r"(r[0]), "=r"(r[1]), "=r"(r[2]), "=r"(r[3]) : "r"(addr));
}

__device__ __forceinline__ void mma16816(float* c, const uint32_t* a,
                                         const uint32_t* b) {
    asm volatile(
        "mma.sync.aligned.m16n8k16.row.col.f32.bf16.bf16.f32 "
        "{%0,%1,%2,%3}, {%4,%5,%6,%7}, {%8,%9}, {%0,%1,%2,%3};"
        : "+f"(c[0]), "+f"(c[1]), "+f"(c[2]), "+f"(c[3])
        : "r"(a[0]), "r"(a[1]), "r"(a[2]), "r"(a[3]), "r"(b[0]), "r"(b[1]));
}

__device__ __forceinline__ void split2(float x, float y, uint32_t& h, uint32_t& l) {
    __nv_bfloat16 hx = __float2bfloat16(x), hy = __float2bfloat16(y);
    __nv_bfloat16 lx = __float2bfloat16(x - __bfloat162float(hx));
    __nv_bfloat16 ly = __float2bfloat16(y - __bfloat162float(hy));
    __nv_bfloat162 th(hx, hy), tl(lx, ly);
    h = *(uint32_t*)&th;
    l = *(uint32_t*)&tl;
}

// ---------------------------------------------------------------------------
// Conversions (fused launches)
// ---------------------------------------------------------------------------
__global__ __launch_bounds__(256) void conv_act3(
    const float* __restrict__ q, const float* __restrict__ k,
    const float* __restrict__ v)
{
    const float* X = blockIdx.y == 0 ? q : (blockIdx.y == 1 ? k : v);
    __nv_bfloat16* hi = g_ah + (size_t)blockIdx.y * ACT_ELEMS;
    __nv_bfloat16* lo = g_al + (size_t)blockIdx.y * ACT_ELEMS;
    int e = (blockIdx.x * 256 + threadIdx.x) * 4;
    float4 x = *(const float4*)(X + e);
    float xs[4] = {x.x, x.y, x.z, x.w};
    union { __nv_bfloat16 b[4]; uint2 u; } ph, pl;
    #pragma unroll
    for (int j = 0; j < 4; j++) {
        __nv_bfloat16 h = __float2bfloat16(xs[j]);
        ph.b[j] = h;
        pl.b[j] = __float2bfloat16(xs[j] - __bfloat162float(h));
    }
    *(uint2*)(hi + e) = ph.u;
    *(uint2*)(lo + e) = pl.u;
}

__global__ void conv_wt4(const float* __restrict__ Wq, const float* __restrict__ Wk,
                         const float* __restrict__ Wv, const float* __restrict__ Wo)
{
    __shared__ float t[32][33];
    const int z = blockIdx.z;
    const float* W = z == 0 ? Wq : (z == 1 ? Wk : (z == 2 ? Wv : Wo));
    __nv_bfloat16* hi = g_wh + (size_t)z * W_ELEMS;
    __nv_bfloat16* lo = g_wl + (size_t)z * W_ELEMS;
    int n0 = blockIdx.x * 32, k0 = blockIdx.y * 32;
    int tx = threadIdx.x, ty = threadIdx.y;  // 32 x 8

    #pragma unroll
    for (int j = 0; j < 32; j += 8)
        t[ty + j][tx] = W[(size_t)(k0 + ty + j) * 1024 + n0 + tx];
    __syncthreads();

    #pragma unroll
    for (int j = 0; j < 32; j += 8) {
        int n = n0 + ty + j, k = k0 + tx;
        float x = t[tx][ty + j];
        __nv_bfloat16 h = __float2bfloat16(x);
        __nv_bfloat16 l = __float2bfloat16(x - __bfloat162float(h));
        hi[(size_t)n * 1024 + k] = h;
        lo[(size_t)n * 1024 + k] = l;
    }
}

// ---------------------------------------------------------------------------
// HMMA GEMM body, bf16 hi/lo split (3-term).
// ---------------------------------------------------------------------------
#define ROWB 80
#define ARR_B (128 * ROWB)
#define STAGE_B (4 * ARR_B)
#define GEMM_SMEM (2 * STAGE_B)

__device__ __forceinline__ void gemm_load_stage(
    uint32_t dbase, int m0, int n0, int k0, int tid,
    const __nv_bfloat16* Ah, const __nv_bfloat16* Al,
    const __nv_bfloat16* Bh, const __nv_bfloat16* Bl)
{
    int ldc = tid & 3;
    int r0 = tid >> 2;
    #pragma unroll
    for (int h = 0; h < 2; h++) {
        int row = r0 + h * 64;
        uint32_t doff = dbase + row * ROWB + ldc * 16;
        size_t ga = (size_t)(m0 + row) * 1024 + k0 + ldc * 8;
        size_t gb = (size_t)(n0 + row) * 1024 + k0 + ldc * 8;
        CP16(doff,             Ah + ga);
        CP16(doff + ARR_B,     Al + ga);
        CP16(doff + 2 * ARR_B, Bh + gb);
        CP16(doff + 3 * ARR_B, Bl + gb);
    }
}

template <bool OUT_BF16>
__device__ __forceinline__ void gemm_body(
    const __nv_bfloat16* __restrict__ Ah, const __nv_bfloat16* __restrict__ Al,
    const __nv_bfloat16* __restrict__ Bh, const __nv_bfloat16* __restrict__ Bl,
    const float* __restrict__ bias, float* __restrict__ C,
    __nv_bfloat16* __restrict__ Ch, __nv_bfloat16* __restrict__ Cl,
    float scale, int m0, int n0, char* sm)
{
    const uint32_t sb = smem_u32(sm);
    const int tid = threadIdx.x;
    const int lid = tid & 31, wid = tid >> 5;
    const int wm = wid >> 1, wn = wid & 1;

    float acc[2][8][4];
    #pragma unroll
    for (int f = 0; f < 2; f++)
        #pragma unroll
        for (int n = 0; n < 8; n++)
            #pragma unroll
            for (int j = 0; j < 4; j++) acc[f][n][j] = 0.0f;

    const uint32_t a_rel = (uint32_t)(wm * 32 + (lid & 15)) * ROWB + ((lid >> 4) << 4);
    const uint32_t b_rel = (uint32_t)(wn * 64 + (lid & 7) + ((lid >> 4) << 3)) * ROWB
                           + (((lid >> 3) & 1) << 4);

    gemm_load_stage(sb, m0, n0, 0, tid, Ah, Al, Bh, Bl);
    CP_COMMIT();

    for (int c = 0; c < 32; c++) {
        const int s = c & 1;
        if (c < 31) {
            gemm_load_stage(sb + (s ^ 1) * STAGE_B, m0, n0, (c + 1) * 32, tid,
                            Ah, Al, Bh, Bl);
            CP_COMMIT();
            CP_WAIT1();
        } else {
            CP_WAIT0();
        }
        __syncthreads();

        const uint32_t base = sb + s * STAGE_B;
        #pragma unroll
        for (int ks = 0; ks < 2; ks++) {
            const uint32_t koff = ks * 32;
            uint32_t ah[2][4], al[2][4];
            #pragma unroll
            for (int f = 0; f < 2; f++) {
                ldsm_x4(ah[f], base + a_rel + f * 16 * ROWB + koff);
                ldsm_x4(al[f], base + ARR_B + a_rel + f * 16 * ROWB + koff);
            }
            #pragma unroll
            for (int nfp = 0; nfp < 4; nfp++) {
                uint32_t bh[4], bl[4];
                ldsm_x4(bh, base + 2 * ARR_B + b_rel + nfp * 16 * ROWB + koff);
                ldsm_x4(bl, base + 3 * ARR_B + b_rel + nfp * 16 * ROWB + koff);
                #pragma unroll
                for (int f = 0; f < 2; f++) {
                    mma16816(acc[f][nfp * 2 + 0], ah[f], bh + 0);
                    mma16816(acc[f][nfp * 2 + 0], ah[f], bl + 0);
                    mma16816(acc[f][nfp * 2 + 0], al[f], bh + 0);
                    mma16816(acc[f][nfp * 2 + 1], ah[f], bh + 2);
                    mma16816(acc[f][nfp * 2 + 1], ah[f], bl + 2);
                    mma16816(acc[f][nfp * 2 + 1], al[f], bh + 2);
                }
            }
        }
        __syncthreads();
    }

    const int r_base = m0 + wm * 32 + (lid >> 2);
    const int c_lane = (lid & 3) * 2;
    #pragma unroll
    for (int f = 0; f < 2; f++) {
        #pragma unroll
        for (int nf = 0; nf < 8; nf++) {
            int col = n0 + wn * 64 + nf * 8 + c_lane;
            float2 bb = *(const float2*)(bias + col);
            int r0 = r_base + f * 16;
            float* a = acc[f][nf];
            float v0 = (a[0] + bb.x) * scale, v1 = (a[1] + bb.y) * scale;
            float v2 = (a[2] + bb.x) * scale, v3 = (a[3] + bb.y) * scale;
            if (OUT_BF16) {
                uint32_t h0, l0, h1, l1;
                split2(v0, v1, h0, l0);
                split2(v2, v3, h1, l1);
                *(uint32_t*)(Ch + (size_t)r0 * 1024 + col) = h0;
                *(uint32_t*)(Cl + (size_t)r0 * 1024 + col) = l0;
                *(uint32_t*)(Ch + (size_t)(r0 + 8) * 1024 + col) = h1;
                *(uint32_t*)(Cl + (size_t)(r0 + 8) * 1024 + col) = l1;
            } else {
                *(float2*)(C + (size_t)r0 * 1024 + col) = make_float2(v0, v1);
                *(float2*)(C + (size_t)(r0 + 8) * 1024 + col) = make_float2(v2, v3);
            }
        }
    }
}

// Fused QKV projection: grid (8, 32, 3)
__global__ __launch_bounds__(256, 2) void qkv_gemm(
    const float* __restrict__ bq, const float* __restrict__ bk,
    const float* __restrict__ bv)
{
    extern __shared__ __align__(16) char sm[];
    const int z = blockIdx.z;
    const float* bias = z == 0 ? bq : (z == 1 ? bk : bv);
    gemm_body<true>(g_ah + (size_t)z * ACT_ELEMS, g_al + (size_t)z * ACT_ELEMS,
                    g_wh + (size_t)z * W_ELEMS,  g_wl + (size_t)z * W_ELEMS,
                    bias, nullptr,
                    g_qkvh + (size_t)z * ACT_ELEMS, g_qkvl + (size_t)z * ACT_ELEMS,
                    z == 0 ? 0.125f : 1.0f,
                    blockIdx.y * 128, blockIdx.x * 128, sm);
}

// Output projection: grid (8, 32)
__global__ __launch_bounds__(256, 2) void out_gemm(
    const float* __restrict__ bo, float* __restrict__ out)
{
    extern __shared__ __align__(16) char sm[];
    gemm_body<false>(g_ch, g_cl, g_wh + 3ull * W_ELEMS, g_wl + 3ull * W_ELEMS,
                     bo, out, nullptr, nullptr, 1.0f,
                     blockIdx.y * 128, blockIdx.x * 128, sm);
}

// ---------------------------------------------------------------------------
// Tensor-core flash attention, Q tile 128 rows, 256 threads (8 warps).
// ---------------------------------------------------------------------------
#define KROWB 144                      // 64 bf16 (128B) + 16B pad
#define TILE9K (64 * KROWB)            // 9216 (K/V tiles)
#define QTILE (128 * KROWB)            // 18432
#define BROWB 272                      // 64 fp32 (256B) + 16B pad
#define BIAS_B (128 * BROWB)           // 34816
#define STAGE_A (4 * TILE9K + BIAS_B)  // 71680: Kh,Kl,Vh,Vl,bias
#define Q_OFF (2 * STAGE_A)            // 143360
#define ATTN_SMEM (Q_OFF + 2 * QTILE)  // 180224

__device__ __forceinline__ void attn_load_stage(
    uint32_t dst, int b, int h, int qt, int kt, int tid,
    const float* __restrict__ bias)
{
    const __nv_bfloat16* kh = g_qkvh + 1ull * ACT_ELEMS;
    const __nv_bfloat16* kl = g_qkvl + 1ull * ACT_ELEMS;
    const __nv_bfloat16* vh = g_qkvh + 2ull * ACT_ELEMS;
    const __nv_bfloat16* vl = g_qkvl + 2ull * ACT_ELEMS;
    const size_t krow = (size_t)(b * NN + kt * 64);
    #pragma unroll
    for (int t = 0; t < 2; t++) {
        int chunk = tid + t * 256;
        int r = chunk >> 3, c = chunk & 7;
        size_t g = (krow + r) * DM + h * 64 + c * 8;
        uint32_t d = dst + r * KROWB + c * 16;
        CP16(d,              kh + g);
        CP16(d + TILE9K,     kl + g);
        CP16(d + 2 * TILE9K, vh + g);
        CP16(d + 3 * TILE9K, vl + g);
    }
    const float* bg = bias + (((size_t)(b * NH + h)) * NN + qt * 128) * NN + kt * 64;
    #pragma unroll
    for (int t = 0; t < 8; t++) {
        int chunk = tid + t * 256;
        int r = chunk >> 4, c = chunk & 15;
        CP16(dst + 4 * TILE9K + r * BROWB + c * 16, bg + (size_t)r * NN + c * 4);
    }
}

__global__ __launch_bounds__(256) void attn_mma(const float* __restrict__ bias)
{
    extern __shared__ __align__(16) char sm[];
    const uint32_t sb = smem_u32(sm);
    const int tid = threadIdx.x, lid = tid & 31, wid = tid >> 5;
    const int bh = blockIdx.x;            // b*16 + h
    const int qt = blockIdx.y;            // 0..7 (128-row q tiles)
    const int b = bh >> 4, h = bh & 15;
    const size_t qrow0 = (size_t)(b * NN + qt * 128);

    // Q tile hi/lo (128x64) + stage0/stage1 prefetch
    #pragma unroll
    for (int t = 0; t < 4; t++) {
        int chunk = tid + t * 256;
        int r = chunk >> 3, c = chunk & 7;
        size_t g = (qrow0 + r) * DM + h * 64 + c * 8;
        CP16(sb + Q_OFF + r * KROWB + c * 16, g_qkvh + g);
        CP16(sb + Q_OFF + QTILE + r * KROWB + c * 16, g_qkvl + g);
    }
    attn_load_stage(sb, b, h, qt, 0, tid, bias);
    CP_COMMIT();
    attn_load_stage(sb + STAGE_A, b, h, qt, 1, tid, bias);
    CP_COMMIT();
    CP_WAIT1();
    __syncthreads();

    // Q fragments (warp w owns q rows [16w, 16w+16))
    uint32_t aqh[4][4], aql[4][4];
    {
        const uint32_t qrel = sb + Q_OFF + (uint32_t)(wid * 16 + (lid & 15)) * KROWB
                              + ((lid >> 4) << 4);
        #pragma unroll
        for (int ks = 0; ks < 4; ks++) {
            ldsm_x4(aqh[ks], qrel + ks * 32);
            ldsm_x4(aql[ks], qrel + QTILE + ks * 32);
        }
    }

    float o[8][4];
    #pragma unroll
    for (int j = 0; j < 8; j++)
        #pragma unroll
        for (int e = 0; e < 4; e++) o[j][e] = 0.0f;
    float m0 = -1e30f, m1 = -1e30f, l0 = 0.0f, l1 = 0.0f;

    const int rrow = (lid >> 2);
    const uint32_t krel_lane = (uint32_t)((lid & 7) + ((lid >> 4) << 3)) * KROWB
                               + (((lid >> 3) & 1) << 4);
    const uint32_t vcol_lane = ((lid >> 4) << 4);
    const uint32_t vrow_lane = (uint32_t)(lid & 15) * KROWB;

    for (int kt = 0; kt < 16; kt++) {
        const uint32_t st = sb + (kt & 1) * STAGE_A;
        const uint32_t strel = (kt & 1) * STAGE_A;

        // ---- S = Q K^T ----
        float s[8][4];
        #pragma unroll
        for (int j = 0; j < 8; j++)
            #pragma unroll
            for (int e = 0; e < 4; e++) s[j][e] = 0.0f;

        #pragma unroll
        for (int ks = 0; ks < 4; ks++) {
            const uint32_t kbase = st + krel_lane + ks * 32;
            #pragma unroll
            for (int np = 0; np < 4; np++) {
                uint32_t bkh[4], bkl[4];
                ldsm_x4(bkh, kbase + np * 16 * KROWB);
                ldsm_x4(bkl, kbase + TILE9K + np * 16 * KROWB);
                mma16816(s[2 * np + 0], aqh[ks], bkh + 0);
                mma16816(s[2 * np + 0], aqh[ks], bkl + 0);
                mma16816(s[2 * np + 0], aql[ks], bkh + 0);
                mma16816(s[2 * np + 1], aqh[ks], bkh + 2);
                mma16816(s[2 * np + 1], aqh[ks], bkl + 2);
                mma16816(s[2 * np + 1], aql[ks], bkh + 2);
            }
        }

        // ---- + bias ----
        {
            const char* bsm = sm + strel + 4 * TILE9K
                              + (wid * 16 + rrow) * BROWB + (lid & 3) * 8;
            #pragma unroll
            for (int j = 0; j < 8; j++) {
                float2 b0 = *(const float2*)(bsm + j * 32);
                float2 b1 = *(const float2*)(bsm + 8 * BROWB + j * 32);
                s[j][0] += b0.x; s[j][1] += b0.y;
                s[j][2] += b1.x; s[j][3] += b1.y;
            }
        }

        // ---- online softmax ----
        float mx0 = -1e30f, mx1 = -1e30f;
        #pragma unroll
        for (int j = 0; j < 8; j++) {
            mx0 = fmaxf(mx0, fmaxf(s[j][0], s[j][1]));
            mx1 = fmaxf(mx1, fmaxf(s[j][2], s[j][3]));
        }
        mx0 = fmaxf(mx0, __shfl_xor_sync(0xffffffffu, mx0, 1));
        mx0 = fmaxf(mx0, __shfl_xor_sync(0xffffffffu, mx0, 2));
        mx1 = fmaxf(mx1, __shfl_xor_sync(0xffffffffu, mx1, 1));
        mx1 = fmaxf(mx1, __shfl_xor_sync(0xffffffffu, mx1, 2));

        float mn0 = fmaxf(m0, mx0), mn1 = fmaxf(m1, mx1);
        float sc0 = __expf(m0 - mn0), sc1 = __expf(m1 - mn1);
        m0 = mn0; m1 = mn1;

        float rs0 = 0.0f, rs1 = 0.0f;
        #pragma unroll
        for (int j = 0; j < 8; j++) {
            s[j][0] = __expf(s[j][0] - m0);
            s[j][1] = __expf(s[j][1] - m0);
            s[j][2] = __expf(s[j][2] - m1);
            s[j][3] = __expf(s[j][3] - m1);
            rs0 += s[j][0] + s[j][1];
            rs1 += s[j][2] + s[j][3];
        }
        rs0 += __shfl_xor_sync(0xffffffffu, rs0, 1);
        rs0 += __shfl_xor_sync(0xffffffffu, rs0, 2);
        rs1 += __shfl_xor_sync(0xffffffffu, rs1, 1);
        rs1 += __shfl_xor_sync(0xffffffffu, rs1, 2);
        l0 = l0 * sc0 + rs0;
        l1 = l1 * sc1 + rs1;

        #pragma unroll
        for (int j = 0; j < 8; j++) {
            o[j][0] *= sc0; o[j][1] *= sc0;
            o[j][2] *= sc1; o[j][3] *= sc1;
        }

        // ---- pack P -> bf16 hi/lo A-fragments ----
        uint32_t pah[4][4], pal[4][4];
        #pragma unroll
        for (int ks = 0; ks < 4; ks++) {
            split2(s[2 * ks][0],     s[2 * ks][1],     pah[ks][0], pal[ks][0]);
            split2(s[2 * ks][2],     s[2 * ks][3],     pah[ks][1], pal[ks][1]);
            split2(s[2 * ks + 1][0], s[2 * ks + 1][1], pah[ks][2], pal[ks][2]);
            split2(s[2 * ks + 1][2], s[2 * ks + 1][3], pah[ks][3], pal[ks][3]);
        }

        // ---- O += P V ----
        #pragma unroll
        for (int ks = 0; ks < 4; ks++) {
            const uint32_t vbase = st + 2 * TILE9K + ks * 16 * KROWB
                                   + vrow_lane + vcol_lane;
            #pragma unroll
            for (int np = 0; np < 4; np++) {
                uint32_t bvh[4], bvl[4];
                ldsm_x4_t(bvh, vbase + np * 32);
                ldsm_x4_t(bvl, vbase + TILE9K + np * 32);
                mma16816(o[2 * np + 0], pah[ks], bvh + 0);
                mma16816(o[2 * np + 0], pah[ks], bvl + 0);
                mma16816(o[2 * np + 0], pal[ks], bvh + 0);
                mma16816(o[2 * np + 1], pah[ks], bvh + 2);
                mma16816(o[2 * np + 1], pah[ks], bvl + 2);
                mma16816(o[2 * np + 1], pal[ks], bvh + 2);
            }
        }

        __syncthreads();
        if (kt < 15) {
            if (kt + 2 < 16) {
                attn_load_stage(sb + (kt & 1) * STAGE_A, b, h, qt, kt + 2, tid, bias);
                CP_COMMIT();
                CP_WAIT1();
            } else {
                CP_WAIT0();
            }
            __syncthreads();
        }
    }

    // ---- epilogue -> ctx bf16 hi/lo ----
    const float inv0 = 1.0f / l0, inv1 = 1.0f / l1;
    const size_t grow0 = qrow0 + wid * 16 + rrow;
    #pragma unroll
    for (int j = 0; j < 8; j++) {
        int col = h * 64 + j * 8 + (lid & 3) * 2;
        uint32_t h0, lo0, h1, lo1;
        split2(o[j][0] * inv0, o[j][1] * inv0, h0, lo0);
        split2(o[j][2] * inv1, o[j][3] * inv1, h1, lo1);
        *(uint32_t*)(g_ch + grow0 * DM + col) = h0;
        *(uint32_t*)(g_cl + grow0 * DM + col) = lo0;
        *(uint32_t*)(g_ch + (grow0 + 8) * DM + col) = h1;
        *(uint32_t*)(g_cl + (grow0 + 8) * DM + col) = lo1;
    }
}

// ---------------------------------------------------------------------------
// Launch
// ---------------------------------------------------------------------------
extern "C" void kernel_launch(void* const* d_in, const int* in_sizes, int n_in,
                              void* d_out, int out_size)
{
    const float* queries   = (const float*)d_in[0];
    const float* keys      = (const float*)d_in[1];
    const float* values    = (const float*)d_in[2];
    const float* attn_bias = (const float*)d_in[3];
    const float* Wq = (const float*)d_in[4];
    const float* bq = (const float*)d_in[5];
    const float* Wk = (const float*)d_in[6];
    const float* bk = (const float*)d_in[7];
    const float* Wv = (const float*)d_in[8];
    const float* bv = (const float*)d_in[9];
    const float* Wo = (const float*)d_in[10];
    const float* bo = (const float*)d_in[11];
    float* out = (float*)d_out;

    cudaFuncSetAttribute(attn_mma,
                         cudaFuncAttributeMaxDynamicSharedMemorySize, ATTN_SMEM);
    cudaFuncSetAttribute(qkv_gemm,
                         cudaFuncAttributeMaxDynamicSharedMemorySize, GEMM_SMEM);
    cudaFuncSetAttribute(out_gemm,
                         cudaFuncAttributeMaxDynamicSharedMemorySize, GEMM_SMEM);

    conv_act3<<<dim3(4096, 3), 256>>>(queries, keys, values);
    conv_wt4<<<dim3(32, 32, 4), dim3(32, 8)>>>(Wq, Wk, Wv, Wo);

    qkv_gemm<<<dim3(8, 32, 3), 256, GEMM_SMEM>>>(bq, bk, bv);

    attn_mma<<<dim3(64, 8), 256, ATTN_SMEM>>>(attn_bias);

    out_gemm<<<dim3(8, 32), 256, GEMM_SMEM>>>(bo, out);
}